// round 5
// baseline (speedup 1.0000x reference)
#include <cuda_runtime.h>
#include <math.h>

#define H 1024
#define E 48
#define R 32
#define KC 16          // k-chunks in precompute
#define KCHUNK 64      // H / KC
#define TOTROWS 128    // 48 P + 48 Q + 32 B rows
#define MROWS 8        // rows per precompute block

typedef unsigned long long ull;

// Combined precompute result: [0:48H) = P+b1 rows, [48H:96H) = Q rows, [96H:128H) = B rows
__device__ __align__(16) float g_PQB[TOTROWS * H];
// Per-k-chunk partials (8 MB)
__device__ __align__(16) float g_part[KC * TOTROWS * H];

// ---- packed f32x2 helpers (Blackwell) ------------------------------------
__device__ __forceinline__ ull f2fma(ull a, ull b, ull c) {
    ull d;
    asm("fma.rn.f32x2 %0, %1, %2, %3;" : "=l"(d) : "l"(a), "l"(b), "l"(c));
    return d;
}
__device__ __forceinline__ ull f2add(ull a, ull b) {
    ull d;
    asm("add.rn.f32x2 %0, %1, %2;" : "=l"(d) : "l"(a), "l"(b));
    return d;
}
__device__ __forceinline__ ull f2pack(float lo, float hi) {
    ull d;
    asm("mov.b64 %0, {%1, %2};" : "=l"(d) : "f"(lo), "f"(hi));
    return d;
}
__device__ __forceinline__ void f2unpack(ull v, float& lo, float& hi) {
    asm("mov.b64 {%0, %1}, %2;" : "=f"(lo), "=f"(hi) : "l"(v));
}

// ---------------------------------------------------------------------------
// Kernel 1: partial GEMMs. 4 output columns per thread (2 packed f32x2 accs
// per row), batches of 4 k with LDG.128 double-buffered W prefetch.
// grid = (32, 16): x = kc(16) + 16*nb(2 panels of 512 cols); y = 16 row-groups.
// Per 4-k batch: 4 LDG.128 (W) + 16 LDS.128 (X pairs) + 64 packed FMA.
// ---------------------------------------------------------------------------
__global__ void __launch_bounds__(128, 5)
precompute_kernel(const float* __restrict__ ent,
                  const float* __restrict__ rel,
                  const float* __restrict__ W1)
{
    __shared__ __align__(16) ull xs[MROWS][KCHUNK];   // duplicated {x,x} pairs

    int g   = blockIdx.y;          // 0..15 row group
    int kc  = blockIdx.x & 15;
    int nb  = blockIdx.x >> 4;     // 0..1
    int tid = threadIdx.x;
    int n   = nb * 512 + tid * 4;

    const float* X;
    int xrow, woff, secrow;
    if (g < 6)       { X = ent; xrow = g * 8;        woff = 0;     secrow = g * 8; }
    else if (g < 12) { X = ent; xrow = (g - 6) * 8;  woff = 2 * H; secrow = 48 + (g - 6) * 8; }
    else             { X = rel; xrow = (g - 12) * 8; woff = H;     secrow = 96 + (g - 12) * 8; }

    const int k0 = kc * KCHUNK;
    const float* wbase = W1 + (size_t)(woff + k0) * H + n;

    // prefetch first W batch (4 rows x 4 cols via LDG.128)
    ulonglong2 wc[4];
#pragma unroll
    for (int r = 0; r < 4; r++)
        wc[r] = *(const ulonglong2*)(wbase + (size_t)r * H);

    // stage X chunk: 8*64 = 512 packed entries, 4 per thread
#pragma unroll
    for (int t = 0; t < 4; t++) {
        int idx = tid + t * 128;
        int m  = idx >> 6;
        int kk = idx & 63;
        float v = X[(size_t)(xrow + m) * H + k0 + kk];
        xs[m][kk] = f2pack(v, v);
    }
    __syncthreads();

    ull acc[MROWS][2];
#pragma unroll
    for (int m = 0; m < MROWS; m++) { acc[m][0] = 0ull; acc[m][1] = 0ull; }

#pragma unroll
    for (int b = 0; b < KCHUNK / 4; b++) {
        ulonglong2 wn[4];
        if (b < KCHUNK / 4 - 1) {
#pragma unroll
            for (int r = 0; r < 4; r++)
                wn[r] = *(const ulonglong2*)(wbase + (size_t)((b + 1) * 4 + r) * H);
        }
        int kk = b * 4;
#pragma unroll
        for (int m = 0; m < MROWS; m++) {
            ulonglong2 xa = *(const ulonglong2*)&xs[m][kk];      // k, k+1
            ulonglong2 xb = *(const ulonglong2*)&xs[m][kk + 2];  // k+2, k+3
            acc[m][0] = f2fma(xa.x, wc[0].x, acc[m][0]);
            acc[m][1] = f2fma(xa.x, wc[0].y, acc[m][1]);
            acc[m][0] = f2fma(xa.y, wc[1].x, acc[m][0]);
            acc[m][1] = f2fma(xa.y, wc[1].y, acc[m][1]);
            acc[m][0] = f2fma(xb.x, wc[2].x, acc[m][0]);
            acc[m][1] = f2fma(xb.x, wc[2].y, acc[m][1]);
            acc[m][0] = f2fma(xb.y, wc[3].x, acc[m][0]);
            acc[m][1] = f2fma(xb.y, wc[3].y, acc[m][1]);
        }
#pragma unroll
        for (int r = 0; r < 4; r++) wc[r] = wn[r];
    }

    float* dst = g_part + (size_t)kc * (TOTROWS * H) + (size_t)secrow * H + n;
#pragma unroll
    for (int m = 0; m < MROWS; m++) {
        ulonglong2 v; v.x = acc[m][0]; v.y = acc[m][1];
        *(ulonglong2*)(dst + (size_t)m * H) = v;
    }
}

// ---------------------------------------------------------------------------
// Kernel 2: reduce partials; fold b1 into the P section. L2-hot.
// ---------------------------------------------------------------------------
__global__ void __launch_bounds__(256)
reduce_kernel(const float* __restrict__ b1v)
{
    int idx4 = blockIdx.x * 256 + threadIdx.x;   // < 32768
    const float4* part4 = (const float4*)g_part;
    float4 s = part4[idx4];
#pragma unroll
    for (int c = 1; c < KC; c++) {
        float4 p = part4[(size_t)c * 32768 + idx4];
        s.x += p.x; s.y += p.y; s.z += p.z; s.w += p.w;
    }
    if (idx4 < 48 * 256) {   // P section: fold b1
        float4 bb = ((const float4*)b1v)[idx4 & 255];
        s.x += bb.x; s.y += bb.y; s.z += bb.z; s.w += bb.w;
    }
    ((float4*)g_PQB)[idx4] = s;
}

// ---------------------------------------------------------------------------
// Kernel 3: scores, k-stationary. grid = (8, 48): blockIdx.y = i,
// blockIdx.x = kb (4 relations). Block = 128 thr = 4 warps; warp w owns
// k = kb*4 + w and keeps B_k + W2 in registers across ALL j. Per active j,
// D = P'(i)+Q(j) is staged into double-buffered smem by all threads; each
// warp streams D via 8 LDS.128. One load per output element — L1 floor.
// ---------------------------------------------------------------------------
__global__ void __launch_bounds__(128, 3)
score_kernel(const float* __restrict__ W2,
             const float* __restrict__ b2v,
             const int*   __restrict__ starts,
             const int*   __restrict__ maxd_p,
             float*       __restrict__ out)
{
    __shared__ __align__(16) float Dbuf[2][H];
    __shared__ int jlist[E];
    __shared__ int nact;
    __shared__ unsigned char actmask[E];

    int i    = blockIdx.y;
    int kb   = blockIdx.x;          // 0..7
    int tid  = threadIdx.x;
    int lane = tid & 31;
    int w    = tid >> 5;
    int k    = kb * 4 + w;

    int si   = starts[i];
    int maxd = maxd_p[0];
    float b2 = b2v[0];

    if (tid < E) {
        int sj = starts[tid];
        int d = si - sj; if (d < 0) d = -d;
        actmask[tid] = (tid != i) && (d <= maxd);
    }
    __syncthreads();
    if (tid == 0) {
        int c = 0;
#pragma unroll 1
        for (int j = 0; j < E; j++)
            if (actmask[j]) jlist[c++] = j;
        nact = c;
    }
    __syncthreads();

    // zeros for inactive j (this block's 4 k's only)
    for (int idx = tid; idx < E * 4; idx += 128) {
        int j  = idx >> 2;
        int kk = idx & 3;
        if (!actmask[j])
            out[((size_t)i * E + j) * R + kb * 4 + kk] = 0.f;
    }

    int na = nact;
    if (na == 0) return;

    // P'(i) rows in registers (b1 folded already)
    const float4* P4 = (const float4*)(g_PQB + (size_t)i * H);
    float4 pA = P4[tid];
    float4 pB = P4[tid + 128];

    // B_k and W2 resident in registers: layout q=0..7, ulonglong2 @ lane+32q
    const ulonglong2* Bk  = (const ulonglong2*)(g_PQB + (size_t)(2 * E + k) * H);
    const ulonglong2* W24 = (const ulonglong2*)W2;
    ull b01[8], b23[8], w01[8], w23[8];
#pragma unroll
    for (int q = 0; q < 8; q++) {
        ulonglong2 t = Bk [lane + 32 * q];
        ulonglong2 u = W24[lane + 32 * q];
        b01[q] = t.x; b23[q] = t.y;
        w01[q] = u.x; w23[q] = u.y;
    }

    // stage first j
    {
        const float4* Q4 = (const float4*)(g_PQB + (size_t)(E + jlist[0]) * H);
        float4 qa = Q4[tid], qb = Q4[tid + 128];
        float4 da, db;
        da.x = pA.x + qa.x; da.y = pA.y + qa.y; da.z = pA.z + qa.z; da.w = pA.w + qa.w;
        db.x = pB.x + qb.x; db.y = pB.y + qb.y; db.z = pB.z + qb.z; db.w = pB.w + qb.w;
        ((float4*)Dbuf[0])[tid]       = da;
        ((float4*)Dbuf[0])[tid + 128] = db;
    }
    __syncthreads();

#pragma unroll 1
    for (int it = 0; it < na; it++) {
        int cur = it & 1;
        // prefetch + stage next j into alternate buffer
        if (it + 1 < na) {
            const float4* Q4 = (const float4*)(g_PQB + (size_t)(E + jlist[it + 1]) * H);
            float4 qa = Q4[tid], qb = Q4[tid + 128];
            float4 da, db;
            da.x = pA.x + qa.x; da.y = pA.y + qa.y; da.z = pA.z + qa.z; da.w = pA.w + qa.w;
            db.x = pB.x + qb.x; db.y = pB.y + qb.y; db.z = pB.z + qb.z; db.w = pB.w + qb.w;
            ((float4*)Dbuf[cur ^ 1])[tid]       = da;
            ((float4*)Dbuf[cur ^ 1])[tid + 128] = db;
        }

        // compute this j from Dbuf[cur]
        const ulonglong2* D2 = (const ulonglong2*)Dbuf[cur];
        ull a01 = 0ull, a23 = 0ull;
#pragma unroll
        for (int q = 0; q < 8; q++) {
            ulonglong2 dv = D2[lane + 32 * q];
            ull s01 = f2add(dv.x, b01[q]);
            ull s23 = f2add(dv.y, b23[q]);
            float t0, t1, t2, t3;
            f2unpack(s01, t0, t1);
            f2unpack(s23, t2, t3);
            t0 = fmaxf(t0, 0.f); t1 = fmaxf(t1, 0.f);
            t2 = fmaxf(t2, 0.f); t3 = fmaxf(t3, 0.f);
            a01 = f2fma(f2pack(t0, t1), w01[q], a01);
            a23 = f2fma(f2pack(t2, t3), w23[q], a23);
        }
        float r0, r1, r2, r3;
        f2unpack(a01, r0, r1);
        f2unpack(a23, r2, r3);
        float a = (r0 + r1) + (r2 + r3);
#pragma unroll
        for (int off = 16; off > 0; off >>= 1)
            a += __shfl_xor_sync(0xffffffffu, a, off);
        if (lane == 0) {
            int j = jlist[it];
            float x = a + b2;
            out[((size_t)i * E + j) * R + k] = 1.0f / (1.0f + __expf(-x));
        }
        __syncthreads();
    }
}

// ---------------------------------------------------------------------------
// Inputs (metadata order):
//  0 entity_emb f32[48,1024]  1 rel_emb f32[32,1024]  2 W1 f32[3072,1024]
//  3 b1 f32[1024]  4 W2 f32[1024,1]  5 b2 f32[1]
//  6 entity_starts i32[48]    7 max_distance i32
// Output: f32 [48,48,32]
// ---------------------------------------------------------------------------
extern "C" void kernel_launch(void* const* d_in, const int* in_sizes, int n_in,
                              void* d_out, int out_size)
{
    const float* ent    = (const float*)d_in[0];
    const float* rel    = (const float*)d_in[1];
    const float* W1     = (const float*)d_in[2];
    const float* b1     = (const float*)d_in[3];
    const float* W2     = (const float*)d_in[4];
    const float* b2     = (const float*)d_in[5];
    const int*   starts = (const int*)  d_in[6];
    const int*   maxd   = (const int*)  d_in[7];
    float* out = (float*)d_out;

    precompute_kernel<<<dim3(32, 16), 128>>>(ent, rel, W1);
    reduce_kernel<<<128, 256>>>(b1);
    score_kernel<<<dim3(8, 48), 128>>>(W2, b2, starts, maxd, out);
}

// round 6
// speedup vs baseline: 1.3133x; 1.3133x over previous
#include <cuda_runtime.h>
#include <math.h>

#define H 1024
#define E 48
#define R 32
#define KC 16          // k-chunks in precompute
#define KCHUNK 64      // H / KC
#define TOTROWS 128    // 48 P + 48 Q + 32 B rows
#define MROWS 8        // rows per precompute block
#define SLICEJ 8       // j per score block
#define NSLICE 6       // 48 / SLICEJ

typedef unsigned long long ull;

// Combined precompute result: [0:48H) = P+b1 rows, [48H:96H) = Q rows, [96H:128H) = B rows
__device__ __align__(16) float g_PQB[TOTROWS * H];
// Per-k-chunk partials (8 MB)
__device__ __align__(16) float g_part[KC * TOTROWS * H];
// B transposed for lane=k access: BT4[h4][k] = float4{B[k][4h4..4h4+3]}
__device__ __align__(16) float4 g_BT4[(H / 4) * R];

// ---- packed f32x2 helpers (Blackwell) ------------------------------------
__device__ __forceinline__ ull f2fma(ull a, ull b, ull c) {
    ull d;
    asm("fma.rn.f32x2 %0, %1, %2, %3;" : "=l"(d) : "l"(a), "l"(b), "l"(c));
    return d;
}
__device__ __forceinline__ ull f2add(ull a, ull b) {
    ull d;
    asm("add.rn.f32x2 %0, %1, %2;" : "=l"(d) : "l"(a), "l"(b));
    return d;
}
__device__ __forceinline__ ull f2pack(float lo, float hi) {
    ull d;
    asm("mov.b64 %0, {%1, %2};" : "=l"(d) : "f"(lo), "f"(hi));
    return d;
}
__device__ __forceinline__ void f2unpack(ull v, float& lo, float& hi) {
    asm("mov.b64 {%0, %1}, %2;" : "=f"(lo), "=f"(hi) : "l"(v));
}

// ---------------------------------------------------------------------------
// Kernel 1: partial GEMMs (unchanged from best round). 4 cols/thread,
// LDG.128 double-buffered W prefetch, grid (32, 16), 128 threads.
// ---------------------------------------------------------------------------
__global__ void __launch_bounds__(128, 5)
precompute_kernel(const float* __restrict__ ent,
                  const float* __restrict__ rel,
                  const float* __restrict__ W1)
{
    __shared__ __align__(16) ull xs[MROWS][KCHUNK];   // duplicated {x,x} pairs

    int g   = blockIdx.y;          // 0..15 row group
    int kc  = blockIdx.x & 15;
    int nb  = blockIdx.x >> 4;     // 0..1
    int tid = threadIdx.x;
    int n   = nb * 512 + tid * 4;

    const float* X;
    int xrow, woff, secrow;
    if (g < 6)       { X = ent; xrow = g * 8;        woff = 0;     secrow = g * 8; }
    else if (g < 12) { X = ent; xrow = (g - 6) * 8;  woff = 2 * H; secrow = 48 + (g - 6) * 8; }
    else             { X = rel; xrow = (g - 12) * 8; woff = H;     secrow = 96 + (g - 12) * 8; }

    const int k0 = kc * KCHUNK;
    const float* wbase = W1 + (size_t)(woff + k0) * H + n;

    ulonglong2 wc[4];
#pragma unroll
    for (int r = 0; r < 4; r++)
        wc[r] = *(const ulonglong2*)(wbase + (size_t)r * H);

#pragma unroll
    for (int t = 0; t < 4; t++) {
        int idx = tid + t * 128;
        int m  = idx >> 6;
        int kk = idx & 63;
        float v = X[(size_t)(xrow + m) * H + k0 + kk];
        xs[m][kk] = f2pack(v, v);
    }
    __syncthreads();

    ull acc[MROWS][2];
#pragma unroll
    for (int m = 0; m < MROWS; m++) { acc[m][0] = 0ull; acc[m][1] = 0ull; }

#pragma unroll
    for (int b = 0; b < KCHUNK / 4; b++) {
        ulonglong2 wn[4];
        if (b < KCHUNK / 4 - 1) {
#pragma unroll
            for (int r = 0; r < 4; r++)
                wn[r] = *(const ulonglong2*)(wbase + (size_t)((b + 1) * 4 + r) * H);
        }
        int kk = b * 4;
#pragma unroll
        for (int m = 0; m < MROWS; m++) {
            ulonglong2 xa = *(const ulonglong2*)&xs[m][kk];
            ulonglong2 xb = *(const ulonglong2*)&xs[m][kk + 2];
            acc[m][0] = f2fma(xa.x, wc[0].x, acc[m][0]);
            acc[m][1] = f2fma(xa.x, wc[0].y, acc[m][1]);
            acc[m][0] = f2fma(xa.y, wc[1].x, acc[m][0]);
            acc[m][1] = f2fma(xa.y, wc[1].y, acc[m][1]);
            acc[m][0] = f2fma(xb.x, wc[2].x, acc[m][0]);
            acc[m][1] = f2fma(xb.x, wc[2].y, acc[m][1]);
            acc[m][0] = f2fma(xb.y, wc[3].x, acc[m][0]);
            acc[m][1] = f2fma(xb.y, wc[3].y, acc[m][1]);
        }
#pragma unroll
        for (int r = 0; r < 4; r++) wc[r] = wn[r];
    }

    float* dst = g_part + (size_t)kc * (TOTROWS * H) + (size_t)secrow * H + n;
#pragma unroll
    for (int m = 0; m < MROWS; m++) {
        ulonglong2 v; v.x = acc[m][0]; v.y = acc[m][1];
        *(ulonglong2*)(dst + (size_t)m * H) = v;
    }
}

// ---------------------------------------------------------------------------
// Kernel 2: reduce partials; fold b1 into P section; also emit transposed B.
// ---------------------------------------------------------------------------
__global__ void __launch_bounds__(256)
reduce_kernel(const float* __restrict__ b1v)
{
    int idx4 = blockIdx.x * 256 + threadIdx.x;   // < 32768
    const float4* part4 = (const float4*)g_part;
    float4 s = part4[idx4];
#pragma unroll
    for (int c = 1; c < KC; c++) {
        float4 p = part4[(size_t)c * 32768 + idx4];
        s.x += p.x; s.y += p.y; s.z += p.z; s.w += p.w;
    }
    if (idx4 < 48 * 256) {   // P section: fold b1
        float4 bb = ((const float4*)b1v)[idx4 & 255];
        s.x += bb.x; s.y += bb.y; s.z += bb.z; s.w += bb.w;
    }
    ((float4*)g_PQB)[idx4] = s;

    if (idx4 >= 96 * 256) {  // B section: also write transposed copy
        int rowB = (idx4 >> 8) - 96;   // relation k, 0..31
        int h4   = idx4 & 255;
        g_BT4[h4 * R + rowB] = s;
    }
}

// ---------------------------------------------------------------------------
// Kernel 3: scores, lane = relation. grid = (NSLICE, 48): y = i, x = slice of
// 8 j. 256 threads = 8 warps; warp w owns h in [128w, 128w+128). Per group of
// 4 active j: lane k accumulates sum_h relu(D[j][h]+B[k][h])*W2[h] over its
// h-range; B via LDG.128 of g_BT4 (per-lane), D/W2 via LDS broadcast
// (1 wavefront / 32 lanes). Cross-warp reduce via psum smem.
// ---------------------------------------------------------------------------
__global__ void __launch_bounds__(256)
score_kernel(const float* __restrict__ W2,
             const float* __restrict__ b2v,
             const int*   __restrict__ starts,
             const int*   __restrict__ maxd_p,
             float*       __restrict__ out)
{
    __shared__ __align__(16) float Dsm[SLICEJ][H];   // 32 KB
    __shared__ __align__(16) float W2s[H];           // 4 KB
    __shared__ float psum[8][SLICEJ][32];            // 8 KB
    __shared__ int jl[SLICEJ];
    __shared__ int s_cnt;

    int i     = blockIdx.y;
    int slice = blockIdx.x;
    int j0    = slice * SLICEJ;
    int tid   = threadIdx.x;
    int lane  = tid & 31;
    int w     = tid >> 5;

    int si   = starts[i];
    int maxd = maxd_p[0];

    if (tid == 0) {
        int c = 0;
#pragma unroll
        for (int t = 0; t < SLICEJ; t++) {
            int j = j0 + t;
            int d = si - starts[j]; if (d < 0) d = -d;
            if (j != i && d <= maxd) jl[c++] = j;
        }
        s_cnt = c;
        for (int t = c; t < SLICEJ; t++) jl[t] = (c > 0) ? jl[0] : j0;
    }
    __syncthreads();
    int cnt = s_cnt;

    // zeros for inactive j in this slice
    for (int t = tid; t < SLICEJ * R; t += 256) {
        int jj = t >> 5, k = t & 31;
        int j = j0 + jj;
        int d = si - starts[j]; if (d < 0) d = -d;
        if (!((j != i) && (d <= maxd)))
            out[((size_t)i * E + j) * R + k] = 0.f;
    }
    if (cnt == 0) return;

    int ng   = (cnt + 3) >> 2;
    int npad = ng * 4;

    // stage W2
    for (int t = tid; t < H / 4; t += 256)
        ((float4*)W2s)[t] = ((const float4*)W2)[t];

    // stage D[jslot][h] = P'(i)[h] + Q(j)[h] (padded jslots use jl[0])
    for (int idx = tid; idx < npad * (H / 4); idx += 256) {
        int js = idx >> 8;        // H/4 = 256
        int h4 = idx & 255;
        int j  = jl[js];
        float4 p = ((const float4*)g_PQB)[(size_t)i * (H / 4) + h4];
        float4 q = ((const float4*)g_PQB)[(size_t)(E + j) * (H / 4) + h4];
        float4 dv;
        dv.x = p.x + q.x; dv.y = p.y + q.y; dv.z = p.z + q.z; dv.w = p.w + q.w;
        ((float4*)Dsm[js])[h4] = dv;
    }
    __syncthreads();

#pragma unroll 1
    for (int g = 0; g < ng; g++) {
        ull a01[4], a23[4];
#pragma unroll
        for (int jj = 0; jj < 4; jj++) { a01[jj] = 0ull; a23[jj] = 0ull; }

#pragma unroll 4
        for (int t = 0; t < 32; t++) {
            int h4 = w * 32 + t;
            float4 b  = g_BT4[h4 * R + lane];           // per-lane B[k][4h]
            float4 wv = ((const float4*)W2s)[h4];       // broadcast
            ull b01 = f2pack(b.x, b.y),  b23 = f2pack(b.z, b.w);
            ull w01 = f2pack(wv.x, wv.y), w23 = f2pack(wv.z, wv.w);
#pragma unroll
            for (int jj = 0; jj < 4; jj++) {
                float4 dv = ((const float4*)Dsm[g * 4 + jj])[h4];  // broadcast
                ull s01 = f2add(b01, f2pack(dv.x, dv.y));
                ull s23 = f2add(b23, f2pack(dv.z, dv.w));
                float t0, t1, t2, t3;
                f2unpack(s01, t0, t1);
                f2unpack(s23, t2, t3);
                t0 = fmaxf(t0, 0.f); t1 = fmaxf(t1, 0.f);
                t2 = fmaxf(t2, 0.f); t3 = fmaxf(t3, 0.f);
                a01[jj] = f2fma(f2pack(t0, t1), w01, a01[jj]);
                a23[jj] = f2fma(f2pack(t2, t3), w23, a23[jj]);
            }
        }
#pragma unroll
        for (int jj = 0; jj < 4; jj++) {
            float r0, r1, r2, r3;
            f2unpack(a01[jj], r0, r1);
            f2unpack(a23[jj], r2, r3);
            psum[w][g * 4 + jj][lane] = (r0 + r1) + (r2 + r3);
        }
    }
    __syncthreads();

    // cross-warp reduce + sigmoid + store (active jslots only)
    float b2 = b2v[0];
    for (int t = tid; t < cnt * R; t += 256) {
        int js = t >> 5, k = t & 31;
        float s = 0.f;
#pragma unroll
        for (int ww = 0; ww < 8; ww++) s += psum[ww][js][k];
        float x = s + b2;
        out[((size_t)i * E + jl[js]) * R + k] = 1.0f / (1.0f + __expf(-x));
    }
}

// ---------------------------------------------------------------------------
// Inputs (metadata order):
//  0 entity_emb f32[48,1024]  1 rel_emb f32[32,1024]  2 W1 f32[3072,1024]
//  3 b1 f32[1024]  4 W2 f32[1024,1]  5 b2 f32[1]
//  6 entity_starts i32[48]    7 max_distance i32
// Output: f32 [48,48,32]
// ---------------------------------------------------------------------------
extern "C" void kernel_launch(void* const* d_in, const int* in_sizes, int n_in,
                              void* d_out, int out_size)
{
    const float* ent    = (const float*)d_in[0];
    const float* rel    = (const float*)d_in[1];
    const float* W1     = (const float*)d_in[2];
    const float* b1     = (const float*)d_in[3];
    const float* W2     = (const float*)d_in[4];
    const float* b2     = (const float*)d_in[5];
    const int*   starts = (const int*)  d_in[6];
    const int*   maxd   = (const int*)  d_in[7];
    float* out = (float*)d_out;

    precompute_kernel<<<dim3(32, 16), 128>>>(ent, rel, W1);
    reduce_kernel<<<128, 256>>>(b1);
    score_kernel<<<dim3(NSLICE, E), 256>>>(W2, b2, starts, maxd, out);
}